// round 1
// baseline (speedup 1.0000x reference)
#include <cuda_runtime.h>
#include <cuda_bf16.h>
#include <math.h>

// Problem constants
#define BS   2
#define SEQ  2048
#define DMODEL 1024
#define NH   16
#define HD   64
#define M_GEMM (BS*SEQ)        // 4096
#define N_GEMM (3*DMODEL)      // 3072
#define K_GEMM (DMODEL)        // 1024

#define ELEMS_PER_TENSOR (BS*NH*SEQ*HD)  // 4,194,304 (== BS*SEQ*DMODEL)

// Scratch for Q in [b,h,s,d] layout (16 MB). Device global => allowed (no alloc).
__device__ float g_Qbuf[ELEMS_PER_TENSOR];

// ---------------------------------------------------------------------------
// Kernel 1: QKV projection GEMM with scatter epilogue.
//   qkv[m, n] = sum_k X[m,k] * W[n,k] + bias[n]
//   m = b*SEQ + s ; n = t*1024 + h*64 + d  (t: 0=Q, 1=K, 2=V)
//   dest[b,h,s,d] -> Qbuf / Kout / Vout
// Tiling: 128x128 block tile, BK=16, 256 threads, 8x8 per-thread micro-tile.
// ---------------------------------------------------------------------------
__global__ __launch_bounds__(256)
void qkv_gemm_kernel(const float* __restrict__ X,
                     const float* __restrict__ W,
                     const float* __restrict__ bias,
                     float* __restrict__ Qbuf,
                     float* __restrict__ Kout,
                     float* __restrict__ Vout)
{
    __shared__ float As[16][128];   // [k][m]
    __shared__ float Bs[16][128];   // [k][n]

    const int bm = blockIdx.y * 128;
    const int bn = blockIdx.x * 128;
    const int tid = threadIdx.x;
    const int tx = tid & 15;          // 0..15 -> n micro
    const int ty = tid >> 4;          // 0..15 -> m micro

    // loader mapping: tile = 128 rows x 4 float4-cols; 512 float4 / 256 thr = 2 each
    const int lr = tid >> 2;          // row 0..63 (first half)
    const int lc = (tid & 3) * 4;     // k offset 0,4,8,12

    float acc[8][8];
    #pragma unroll
    for (int i = 0; i < 8; i++)
        #pragma unroll
        for (int j = 0; j < 8; j++) acc[i][j] = 0.f;

    for (int k0 = 0; k0 < K_GEMM; k0 += 16) {
        // Load A (X) tile, transposed into As[k][m]
        #pragma unroll
        for (int half = 0; half < 2; half++) {
            int row = lr + half * 64;
            float4 v = *(const float4*)(&X[(size_t)(bm + row) * K_GEMM + k0 + lc]);
            As[lc + 0][row] = v.x; As[lc + 1][row] = v.y;
            As[lc + 2][row] = v.z; As[lc + 3][row] = v.w;
            float4 w = *(const float4*)(&W[(size_t)(bn + row) * K_GEMM + k0 + lc]);
            Bs[lc + 0][row] = w.x; Bs[lc + 1][row] = w.y;
            Bs[lc + 2][row] = w.z; Bs[lc + 3][row] = w.w;
        }
        __syncthreads();

        #pragma unroll
        for (int kk = 0; kk < 16; kk++) {
            float a[8], b[8];
            #pragma unroll
            for (int i = 0; i < 8; i++) a[i] = As[kk][ty * 8 + i];
            #pragma unroll
            for (int j = 0; j < 8; j++) b[j] = Bs[kk][tx * 8 + j];
            #pragma unroll
            for (int i = 0; i < 8; i++)
                #pragma unroll
                for (int j = 0; j < 8; j++)
                    acc[i][j] += a[i] * b[j];
        }
        __syncthreads();
    }

    // Epilogue: scatter to [b,h,s,d] layout
    #pragma unroll
    for (int i = 0; i < 8; i++) {
        const int m = bm + ty * 8 + i;
        const int b = m >> 11;          // / SEQ
        const int s = m & (SEQ - 1);
        #pragma unroll
        for (int j = 0; j < 8; j++) {
            const int n = bn + tx * 8 + j;
            const int t = n >> 10;            // 0..2
            const int h = (n >> 6) & (NH - 1);
            const int d = n & (HD - 1);
            const size_t idx = (((size_t)(b * NH + h)) * SEQ + s) * HD + d;
            const float v = acc[i][j] + bias[n];
            if (t == 0)      Qbuf[idx] = v;
            else if (t == 1) Kout[idx] = v;
            else             Vout[idx] = v;
        }
    }
}

// ---------------------------------------------------------------------------
// Kernel 2: causal flash attention, fp32.
//   One thread owns one query row (q + acc in registers).
//   Block: 128 threads -> 128 query rows. Key tiles of 64 in smem.
//   grid = (SEQ/128, BS*NH)
// ---------------------------------------------------------------------------
__global__ __launch_bounds__(128)
void attn_kernel(const float* __restrict__ Qbuf,
                 const float* __restrict__ Kbuf,
                 const float* __restrict__ Vbuf,
                 float* __restrict__ Out)
{
    __shared__ float Ks[64][64];
    __shared__ float Vs[64][64];

    const int bh = blockIdx.y;           // 0..31
    const int b  = bh >> 4;
    const int h  = bh & (NH - 1);
    const int qt = blockIdx.x;           // 0..15
    const int tid = threadIdx.x;         // 0..127
    const int qidx = qt * 128 + tid;

    const float* qptr = Qbuf + ((size_t)bh * SEQ + qidx) * HD;
    float q[HD];
    #pragma unroll
    for (int i = 0; i < HD / 4; i++) {
        float4 v = *(const float4*)(qptr + i * 4);
        q[4*i+0] = v.x; q[4*i+1] = v.y; q[4*i+2] = v.z; q[4*i+3] = v.w;
    }

    float acc[HD];
    #pragma unroll
    for (int d = 0; d < HD; d++) acc[d] = 0.f;
    float mrow = -INFINITY, lsum = 0.f;

    const float* Kb = Kbuf + (size_t)bh * SEQ * HD;
    const float* Vb = Vbuf + (size_t)bh * SEQ * HD;

    const int ktmax = 2 * qt + 1;   // last key tile index touching this q tile

    for (int kt = 0; kt <= ktmax; kt++) {
        // cooperative tile load: 64x64 floats = 1024 float4 / 128 threads = 8 each
        const size_t base = (size_t)kt * 64 * HD;
        #pragma unroll
        for (int r = 0; r < 8; r++) {
            const int fidx = tid + r * 128;        // 0..1023
            const int row = fidx >> 4;
            const int c   = (fidx & 15) * 4;
            *(float4*)(&Ks[row][c]) = *(const float4*)(Kb + base + row * HD + c);
            *(float4*)(&Vs[row][c]) = *(const float4*)(Vb + base + row * HD + c);
        }
        __syncthreads();

        int jmax = qidx - kt * 64 + 1;
        if (jmax > 64) jmax = 64;
        for (int j = 0; j < jmax; j++) {
            float s = 0.f;
            #pragma unroll
            for (int d = 0; d < HD; d++) s += q[d] * Ks[j][d];
            s *= 0.125f;   // 1/sqrt(64)

            if (s > mrow) {
                const float alpha = __expf(mrow - s);   // exp(-inf)=0 handles init
                lsum *= alpha;
                #pragma unroll
                for (int d = 0; d < HD; d++) acc[d] *= alpha;
                mrow = s;
            }
            const float p = __expf(s - mrow);
            lsum += p;
            #pragma unroll
            for (int d = 0; d < HD; d++) acc[d] += p * Vs[j][d];
        }
        __syncthreads();
    }

    const float inv = 1.0f / lsum;
    float* op = Out + ((size_t)b * SEQ + qidx) * DMODEL + h * HD;
    #pragma unroll
    for (int d = 0; d < HD / 4; d++) {
        float4 v;
        v.x = acc[4*d+0] * inv; v.y = acc[4*d+1] * inv;
        v.z = acc[4*d+2] * inv; v.w = acc[4*d+3] * inv;
        *(float4*)(op + 4 * d) = v;
    }
}

// ---------------------------------------------------------------------------
extern "C" void kernel_launch(void* const* d_in, const int* in_sizes, int n_in,
                              void* d_out, int out_size)
{
    const float* X    = (const float*)d_in[0];   // [2,2048,1024]
    const float* Wqkv = (const float*)d_in[1];   // [3072,1024]
    const float* bqkv = (const float*)d_in[2];   // [3072]

    float* out  = (float*)d_out;                              // [2,2048,1024]
    float* Kout = (float*)d_out + ELEMS_PER_TENSOR;           // [2,16,2048,64]
    float* Vout = (float*)d_out + 2 * (size_t)ELEMS_PER_TENSOR;

    float* Qbuf;
    cudaGetSymbolAddress((void**)&Qbuf, g_Qbuf);

    dim3 ggrid(N_GEMM / 128, M_GEMM / 128);   // (24, 32)
    qkv_gemm_kernel<<<ggrid, 256>>>(X, Wqkv, bqkv, Qbuf, Kout, Vout);

    dim3 agrid(SEQ / 128, BS * NH);           // (16, 32)
    attn_kernel<<<agrid, 128>>>(Qbuf, Kout, Vout, out);
}